// round 9
// baseline (speedup 1.0000x reference)
#include <cuda_runtime.h>
#include <cuda_fp16.h>
#include <cstdint>

#define DD    64
#define HATTN 256
#define NMAX  2048

// ---------------- device-global scratch (no allocs allowed) ----------------
__device__ float  g_Wqa[DD * HATTN];
__device__ float  g_Wka[DD * HATTN];
__device__ float  g_W12[DD * HATTN];      // (pW2@aW1)[h][c]
__device__ float  g_bqa[HATTN];
__device__ float  g_qa [NMAX * HATTN];    // fp32
__device__ __half g_d16[NMAX * DD];       // d_j = pos_j @ pW1 (no bias)
// fragment-ordered fp16 data images (one coalesced LDG.64 per fragment):
__device__ uint2  g_kaf[(NMAX / 16) * 8 * 4 * 32];  // ka: [rb][chk][nt][lane]
__device__ uint2  g_vsf[(NMAX / 16) * 8 * 32];      // vs=x@Wv: [rb][nt2][lane]
// fp16 B-fragment weight images: uint2 = {half2(k0,k0+1), half2(k0+8,k0+9)} at col n0
__device__ uint2  g_W1f [4096];           // W12 : K=64 [kk=4][ntg=32][lane=32]
__device__ uint2  g_aW2f[4096];           // aW2 : K=256 [kk=16][nt=8][lane=32]
__device__ uint2  g_pW2f[1024];           // pW2 : K=64 [kk=4][nt=8][lane=32] (stays gmem, L1-hot)

__device__ __forceinline__ unsigned fp2h2(float a, float b) {
    __half2 h = __floats2half2_rn(a, b);
    return *reinterpret_cast<unsigned*>(&h);
}
__device__ __forceinline__ void mma16(float* c, const unsigned* a, uint2 b) {
    asm volatile("mma.sync.aligned.m16n8k16.row.col.f32.f16.f16.f32 "
                 "{%0,%1,%2,%3}, {%4,%5,%6,%7}, {%8,%9}, {%0,%1,%2,%3};"
                 : "+f"(c[0]), "+f"(c[1]), "+f"(c[2]), "+f"(c[3])
                 : "r"(a[0]), "r"(a[1]), "r"(a[2]), "r"(a[3]), "r"(b.x), "r"(b.y));
}

// ---------------------------------------------------------------------------
// prep1: weight folds W12 = pW2@aW1, Wqa = Wq@aW1, Wka = Wk@aW1, bqa.
// ---------------------------------------------------------------------------
__global__ void prep1(const float* __restrict__ Wq, const float* __restrict__ Wk,
                      const float* __restrict__ pW2, const float* __restrict__ aW1,
                      const float* __restrict__ ab1, const float* __restrict__ pb2)
{
    __shared__ float srow[3][DD];
    const int r = blockIdx.x, c = threadIdx.x;
    if (c < 64)       srow[0][c]       = Wq [r * DD + c];
    else if (c < 128) srow[1][c - 64]  = Wk [r * DD + (c - 64)];
    else if (c < 192) srow[2][c - 128] = pW2[r * DD + (c - 128)];
    __syncthreads();
    float wq = 0.f, wk = 0.f, w12 = 0.f;
    #pragma unroll 8
    for (int t = 0; t < DD; ++t) {
        float a = aW1[t * HATTN + c];
        wq  = fmaf(srow[0][t], a, wq);
        wk  = fmaf(srow[1][t], a, wk);
        w12 = fmaf(srow[2][t], a, w12);
    }
    g_Wqa[r * HATTN + c] = wq;
    g_Wka[r * HATTN + c] = wk;
    g_W12[r * HATTN + c] = w12;
    if (r == 0) {
        float b = ab1[c];
        for (int t = 0; t < DD; ++t) b = fmaf(pb2[t], aW1[t * HATTN + c], b);
        g_bqa[c] = b;
    }
}

// ---------------------------------------------------------------------------
// prepF: pack W12 / aW2 / pW2 into fp16 B-fragment images (9216 entries).
// ---------------------------------------------------------------------------
__global__ void prepF(const float* __restrict__ aW2, const float* __restrict__ pW2)
{
    const int e = blockIdx.x * 256 + threadIdx.x;
    const int lane = e & 31, gg = lane >> 2, tg = lane & 3;
    if (e < 4096) {                                      // W12, K=64, N=256
        const int kk = e >> 10, nt = (e >> 5) & 31;
        const int k0 = 16 * kk + 2 * tg, n0 = 8 * nt + gg;
        uint2 v;
        v.x = fp2h2(g_W12[(k0    ) * HATTN + n0], g_W12[(k0 + 1) * HATTN + n0]);
        v.y = fp2h2(g_W12[(k0 + 8) * HATTN + n0], g_W12[(k0 + 9) * HATTN + n0]);
        g_W1f[e] = v;
    } else if (e < 8192) {                               // aW2, K=256, N=64
        const int l = e - 4096;
        const int kk = l >> 8, nt = (l >> 5) & 7;
        const int k0 = 16 * kk + 2 * tg, n0 = 8 * nt + gg;
        uint2 v;
        v.x = fp2h2(aW2[(k0    ) * DD + n0], aW2[(k0 + 1) * DD + n0]);
        v.y = fp2h2(aW2[(k0 + 8) * DD + n0], aW2[(k0 + 9) * DD + n0]);
        g_aW2f[l] = v;
    } else if (e < 9216) {                               // pW2, K=64, N=64
        const int l = e - 8192;
        const int kk = l >> 8, nt = (l >> 5) & 7;
        const int k0 = 16 * kk + 2 * tg, n0 = 8 * nt + gg;
        uint2 v;
        v.x = fp2h2(pW2[(k0    ) * DD + n0], pW2[(k0 + 1) * DD + n0]);
        v.y = fp2h2(pW2[(k0 + 8) * DD + n0], pW2[(k0 + 9) * DD + n0]);
        g_pW2f[l] = v;
    }
}

// ---------------------------------------------------------------------------
// prep2: qa (fp32), d (fp16), ka/vs in fragment-ordered fp16. grid N x 256.
// ---------------------------------------------------------------------------
__global__ void prep2(const float* __restrict__ x, const float* __restrict__ pos,
                      const float* __restrict__ Wv, const float* __restrict__ pW1,
                      int N)
{
    __shared__ float sx[DD];
    const int n = blockIdx.x, c = threadIdx.x;
    if (c < DD) sx[c] = x[n * DD + c];
    __syncthreads();
    float aq = g_bqa[c], ak = 0.f;
    #pragma unroll 8
    for (int t = 0; t < DD; ++t) {
        float xv = sx[t];
        aq = fmaf(xv, g_Wqa[t * HATTN + c], aq);
        ak = fmaf(xv, g_Wka[t * HATTN + c], ak);
    }
    g_qa[n * HATTN + c] = aq;
    const int rb = n >> 4, rr = n & 15, gg = rr & 7, hi = rr >> 3;
    {
        const int chk = c >> 5, nt = (c >> 3) & 3, tg = (c & 7) >> 1, lo = c & 1;
        const int ent = ((rb * 8 + chk) * 4 + nt) * 32 + (gg * 4 + tg);
        reinterpret_cast<__half*>(g_kaf)[ent * 4 + hi * 2 + lo] = __float2half(ak);
    }
    if (c < DD) {
        float av = 0.f;
        for (int t = 0; t < DD; ++t) av = fmaf(sx[t], Wv[t * DD + c], av);
        const int nt2 = c >> 3, tg = (c & 7) >> 1, lo = c & 1;
        const int ent = (rb * 8 + nt2) * 32 + (gg * 4 + tg);
        reinterpret_cast<__half*>(g_vsf)[ent * 4 + hi * 2 + lo] = __float2half(av);
        g_d16[n * DD + c] = __float2half(fmaf(pos[2 * n], pW1[c],
                                              pos[2 * n + 1] * pW1[DD + c]));
    }
}

// ---------------------------------------------------------------------------
// main: one CTA (128 threads, 4 warps) per query i; warp covers 32 rows
// (mt=2) of each 128-row tile -> B-fragments amortized 2x. 3 CTAs/SM.
// ---------------------------------------------------------------------------
#define OFF_W1F  0
#define OFF_AW2F 32768
#define OFF_QA   65536
#define OFF_CI   66560
#define OFF_REDS 66816
#define OFF_REDA 67840
#define SMEM_SZ  68864

__global__ void __launch_bounds__(128, 3)
pt_main(const float* __restrict__ pos, const float* __restrict__ pW1,
        const float* __restrict__ pb1, const float* __restrict__ pb2,
        float* __restrict__ out, int N)
{
    extern __shared__ char smem[];
    uint2* sW1f  = (uint2*)(smem + OFF_W1F);
    uint2* sAW2f = (uint2*)(smem + OFF_AW2F);
    float* sQa   = (float*)(smem + OFF_QA);
    float* sCi   = (float*)(smem + OFF_CI);
    float* sRedS = (float*)(smem + OFF_REDS);
    float* sRedA = (float*)(smem + OFF_REDA);

    const int tid  = threadIdx.x;
    const int i    = blockIdx.x;
    const int w    = tid >> 5, lane = tid & 31;
    const int g    = lane >> 2, tig = lane & 3;

    {   // stage weight fragment images
        uint4* d1 = (uint4*)sW1f;   const uint4* s1 = (const uint4*)g_W1f;
        uint4* d2 = (uint4*)sAW2f;  const uint4* s2 = (const uint4*)g_aW2f;
        for (int k = tid; k < 2048; k += 128) { d1[k] = s1[k]; d2[k] = s2[k]; }
    }
    sQa[tid]       = g_qa[i * HATTN + tid];
    sQa[tid + 128] = g_qa[i * HATTN + tid + 128];
    const float posIx = pos[2 * i], posIy = pos[2 * i + 1];
    if (tid < 64)
        sCi[tid] = fmaf(posIx, pW1[tid], fmaf(posIy, pW1[DD + tid], pb1[tid]));
    sRedS[tid] = 0.f; sRedS[tid + 128] = 0.f;
    sRedA[tid] = 0.f; sRedA[tid + 128] = 0.f;
    __syncthreads();

    const int ntile = N >> 7;                 // 128 rows per tile; warp = 32 rows
    for (int jt = 0; jt < ntile; ++jt) {
        const int rb0 = jt * 8 + w * 2;       // two 16-row blocks per warp

        // ---- A fragments: U = relu(ci - d_j), K=64, mt=2 ----
        unsigned Af[2][4][4];
        #pragma unroll
        for (int kk = 0; kk < 4; ++kk) {
            const float c0 = sCi[16 * kk + 2 * tig];
            const float c1 = sCi[16 * kk + 2 * tig + 1];
            const float c2 = sCi[16 * kk + 2 * tig + 8];
            const float c3 = sCi[16 * kk + 2 * tig + 9];
            #pragma unroll
            for (int mt = 0; mt < 2; ++mt) {
                const int rlo = (rb0 + mt) * 16 + g, rhi = rlo + 8;
                float2 dl0 = __half22float2(*(const __half2*)&g_d16[rlo * DD + 16 * kk + 2 * tig]);
                float2 dl1 = __half22float2(*(const __half2*)&g_d16[rlo * DD + 16 * kk + 2 * tig + 8]);
                float2 dh0 = __half22float2(*(const __half2*)&g_d16[rhi * DD + 16 * kk + 2 * tig]);
                float2 dh1 = __half22float2(*(const __half2*)&g_d16[rhi * DD + 16 * kk + 2 * tig + 8]);
                Af[mt][kk][0] = fp2h2(fmaxf(c0 - dl0.x, 0.f), fmaxf(c1 - dl0.y, 0.f));
                Af[mt][kk][1] = fp2h2(fmaxf(c0 - dh0.x, 0.f), fmaxf(c1 - dh0.y, 0.f));
                Af[mt][kk][2] = fp2h2(fmaxf(c2 - dl1.x, 0.f), fmaxf(c3 - dl1.y, 0.f));
                Af[mt][kk][3] = fp2h2(fmaxf(c2 - dh1.x, 0.f), fmaxf(c3 - dh1.y, 0.f));
            }
        }

        float sc[2][8][4];
        #pragma unroll
        for (int mt = 0; mt < 2; ++mt)
            #pragma unroll
            for (int a = 0; a < 8; ++a)
                { sc[mt][a][0]=0.f; sc[mt][a][1]=0.f; sc[mt][a][2]=0.f; sc[mt][a][3]=0.f; }

        #pragma unroll 1
        for (int chk = 0; chk < 8; ++chk) {              // 32 attn channels / chunk
            // GEMM1: P = U @ W12 (K=64), both m-tiles share B
            float pa[2][4][4];
            #pragma unroll
            for (int mt = 0; mt < 2; ++mt)
                #pragma unroll
                for (int a = 0; a < 4; ++a)
                    { pa[mt][a][0]=0.f; pa[mt][a][1]=0.f; pa[mt][a][2]=0.f; pa[mt][a][3]=0.f; }
            #pragma unroll
            for (int kk = 0; kk < 4; ++kk) {
                uint2 b0 = sW1f[((kk * 32) + (chk * 4 + 0)) * 32 + lane];
                uint2 b1 = sW1f[((kk * 32) + (chk * 4 + 1)) * 32 + lane];
                uint2 b2 = sW1f[((kk * 32) + (chk * 4 + 2)) * 32 + lane];
                uint2 b3 = sW1f[((kk * 32) + (chk * 4 + 3)) * 32 + lane];
                #pragma unroll
                for (int mt = 0; mt < 2; ++mt) {
                    mma16(pa[mt][0], Af[mt][kk], b0);
                    mma16(pa[mt][1], Af[mt][kk], b1);
                    mma16(pa[mt][2], Af[mt][kk], b2);
                    mma16(pa[mt][3], Af[mt][kk], b3);
                }
            }
            // epilogue: + qa - ka, relu, repack as GEMM2 A-frags
            unsigned a2[2][2][4];
            #pragma unroll
            for (int nt = 0; nt < 4; ++nt) {
                float2 qa2 = *(const float2*)&sQa[chk * 32 + nt * 8 + 2 * tig];
                #pragma unroll
                for (int mt = 0; mt < 2; ++mt) {
                    uint2 kafr = __ldg(&g_kaf[(((rb0 + mt) * 8 + chk) * 4 + nt) * 32 + lane]);
                    float2 kl = __half22float2(*(const __half2*)&kafr.x);
                    float2 kh = __half22float2(*(const __half2*)&kafr.y);
                    float v00 = fmaxf(pa[mt][nt][0] + qa2.x - kl.x, 0.f);
                    float v01 = fmaxf(pa[mt][nt][1] + qa2.y - kl.y, 0.f);
                    float v10 = fmaxf(pa[mt][nt][2] + qa2.x - kh.x, 0.f);
                    float v11 = fmaxf(pa[mt][nt][3] + qa2.y - kh.y, 0.f);
                    const int kk2 = nt >> 1, sl = (nt & 1) << 1;
                    a2[mt][kk2][sl]     = fp2h2(v00, v01);
                    a2[mt][kk2][sl + 1] = fp2h2(v10, v11);
                }
            }
            // GEMM2 partial: sim += P' @ aW2 (K=32 this chunk), B shared by both mts
            #pragma unroll
            for (int kk2 = 0; kk2 < 2; ++kk2)
                #pragma unroll
                for (int nt2 = 0; nt2 < 8; ++nt2) {
                    uint2 b = sAW2f[(((chk * 2 + kk2) * 8) + nt2) * 32 + lane];
                    mma16(sc[0][nt2], a2[0][kk2], b);
                    mma16(sc[1][nt2], a2[1][kk2], b);
                }
        }

        // GEMM3 + exp + accumulate, per m-tile (keeps ra at 32 regs)
        float Sr[16], Ar[16];
        #pragma unroll
        for (int q = 0; q < 16; ++q) { Sr[q] = 0.f; Ar[q] = 0.f; }
        #pragma unroll 1
        for (int mt = 0; mt < 2; ++mt) {
            const int rb = rb0 + mt;
            float ra[8][4];
            #pragma unroll
            for (int a = 0; a < 8; ++a)
                { ra[a][0]=0.f; ra[a][1]=0.f; ra[a][2]=0.f; ra[a][3]=0.f; }
            #pragma unroll
            for (int kk = 0; kk < 4; ++kk)
                #pragma unroll
                for (int nt = 0; nt < 8; ++nt) {
                    uint2 b = __ldg(&g_pW2f[(kk * 8 + nt) * 32 + lane]);
                    mma16(ra[nt], Af[mt][kk], b);
                }
            #pragma unroll
            for (int nt2 = 0; nt2 < 8; ++nt2) {
                uint2 vsfr = __ldg(&g_vsf[(rb * 8 + nt2) * 32 + lane]);
                float2 vl = __half22float2(*(const __half2*)&vsfr.x);
                float2 vh = __half22float2(*(const __half2*)&vsfr.y);
                float e0 = __expf(sc[mt][nt2][0]);
                float e1 = __expf(sc[mt][nt2][1]);
                float e2 = __expf(sc[mt][nt2][2]);
                float e3 = __expf(sc[mt][nt2][3]);
                Sr[nt2 * 2 + 0] += e0 + e2;
                Sr[nt2 * 2 + 1] += e1 + e3;
                Ar[nt2 * 2 + 0] += e0 * (vl.x + ra[nt2][0]) + e2 * (vh.x + ra[nt2][2]);
                Ar[nt2 * 2 + 1] += e1 * (vl.y + ra[nt2][1]) + e3 * (vh.y + ra[nt2][3]);
            }
        }

        // one shfl-reduce per 32 rows
        #pragma unroll
        for (int q = 0; q < 16; ++q) {
            float s = Sr[q], a = Ar[q];
            s += __shfl_xor_sync(0xffffffffu, s, 4);
            a += __shfl_xor_sync(0xffffffffu, a, 4);
            s += __shfl_xor_sync(0xffffffffu, s, 8);
            a += __shfl_xor_sync(0xffffffffu, a, 8);
            s += __shfl_xor_sync(0xffffffffu, s, 16);
            a += __shfl_xor_sync(0xffffffffu, a, 16);
            Sr[q] = s; Ar[q] = a;
        }
        if (lane < 4) {
            #pragma unroll
            for (int nt2 = 0; nt2 < 8; ++nt2) {
                const int d0 = w * DD + nt2 * 8 + 2 * lane;
                sRedS[d0]     += Sr[nt2 * 2 + 0];
                sRedS[d0 + 1] += Sr[nt2 * 2 + 1];
                sRedA[d0]     += Ar[nt2 * 2 + 0];
                sRedA[d0 + 1] += Ar[nt2 * 2 + 1];
            }
        }
    }

    __syncthreads();
    if (tid < DD) {
        float s = 0.f, a = 0.f;
        #pragma unroll
        for (int q = 0; q < 4; ++q) { s += sRedS[q * DD + tid]; a += sRedA[q * DD + tid]; }
        out[i * DD + tid] = a / s + pb2[tid];
    }
}

// ---------------------------------------------------------------------------
extern "C" void kernel_launch(void* const* d_in, const int* in_sizes, int n_in,
                              void* d_out, int out_size)
{
    const float* x   = (const float*)d_in[0];
    const float* pos = (const float*)d_in[1];
    const float* Wq  = (const float*)d_in[2];
    const float* Wk  = (const float*)d_in[3];
    const float* Wv  = (const float*)d_in[4];
    const float* pW1 = (const float*)d_in[5];
    const float* pb1 = (const float*)d_in[6];
    const float* pW2 = (const float*)d_in[7];
    const float* pb2 = (const float*)d_in[8];
    const float* aW1 = (const float*)d_in[9];
    const float* ab1 = (const float*)d_in[10];
    const float* aW2 = (const float*)d_in[11];
    // d_in[12] = ab2: constant over j -> softmax-invariant -> unused.

    const int N = in_sizes[0] / DD;   // B = 1
    float* out  = (float*)d_out;

    prep1<<<DD, 256>>>(Wq, Wk, pW2, aW1, ab1, pb2);
    prepF<<<36, 256>>>(aW2, pW2);
    prep2<<<N, 256>>>(x, pos, Wv, pW1, N);

    cudaFuncSetAttribute((const void*)pt_main,
                         cudaFuncAttributeMaxDynamicSharedMemorySize, SMEM_SZ);
    pt_main<<<N, 128, SMEM_SZ>>>(pos, pW1, pb1, pb2, out, N);
}

// round 10
// speedup vs baseline: 1.0156x; 1.0156x over previous
#include <cuda_runtime.h>
#include <cuda_fp16.h>
#include <cstdint>

#define DD    64
#define HATTN 256
#define NMAX  2048

// ---------------- device-global scratch (no allocs allowed) ----------------
__device__ float  g_Wqa[DD * HATTN];
__device__ float  g_Wka[DD * HATTN];
__device__ float  g_W12[DD * HATTN];      // (pW2@aW1)[h][c]
__device__ float  g_bqa[HATTN];
__device__ float  g_qa [NMAX * HATTN];    // fp32
__device__ __half g_d16[NMAX * DD];       // d_j = pos_j @ pW1 (no bias)
// fragment-ordered fp16 data images (one coalesced LDG.64 per fragment):
__device__ uint2  g_kaf[(NMAX / 16) * 8 * 4 * 32];  // ka: [rb][chk][nt][lane]
__device__ uint2  g_vsf[(NMAX / 16) * 8 * 32];      // vs=x@Wv: [rb][nt2][lane]
// fp16 B-fragment weight images: uint2 = {half2(k0,k0+1), half2(k0+8,k0+9)} at col n0
__device__ uint2  g_W1f [4096];           // W12 : K=64 [kk=4][ntg=32][lane=32]
__device__ uint2  g_aW2f[4096];           // aW2 : K=256 [kk=16][nt=8][lane=32]
__device__ uint2  g_pW2f[1024];           // pW2 : K=64 [kk=4][nt=8][lane=32]

__device__ __forceinline__ unsigned fp2h2(float a, float b) {
    __half2 h = __floats2half2_rn(a, b);
    return *reinterpret_cast<unsigned*>(&h);
}
__device__ __forceinline__ void mma16(float* c, const unsigned* a, uint2 b) {
    asm volatile("mma.sync.aligned.m16n8k16.row.col.f32.f16.f16.f32 "
                 "{%0,%1,%2,%3}, {%4,%5,%6,%7}, {%8,%9}, {%0,%1,%2,%3};"
                 : "+f"(c[0]), "+f"(c[1]), "+f"(c[2]), "+f"(c[3])
                 : "r"(a[0]), "r"(a[1]), "r"(a[2]), "r"(a[3]), "r"(b.x), "r"(b.y));
}
__device__ __forceinline__ void mma16h(unsigned* d, const unsigned* a, uint2 b) {
    asm volatile("mma.sync.aligned.m16n8k16.row.col.f16.f16.f16.f16 "
                 "{%0,%1}, {%2,%3,%4,%5}, {%6,%7}, {%0,%1};"
                 : "+r"(d[0]), "+r"(d[1])
                 : "r"(a[0]), "r"(a[1]), "r"(a[2]), "r"(a[3]), "r"(b.x), "r"(b.y));
}

// ---------------------------------------------------------------------------
// prep1: weight folds W12 = pW2@aW1, Wqa = Wq@aW1, Wka = Wk@aW1, bqa.
// ---------------------------------------------------------------------------
__global__ void prep1(const float* __restrict__ Wq, const float* __restrict__ Wk,
                      const float* __restrict__ pW2, const float* __restrict__ aW1,
                      const float* __restrict__ ab1, const float* __restrict__ pb2)
{
    __shared__ float srow[3][DD];
    const int r = blockIdx.x, c = threadIdx.x;
    if (c < 64)       srow[0][c]       = Wq [r * DD + c];
    else if (c < 128) srow[1][c - 64]  = Wk [r * DD + (c - 64)];
    else if (c < 192) srow[2][c - 128] = pW2[r * DD + (c - 128)];
    __syncthreads();
    float wq = 0.f, wk = 0.f, w12 = 0.f;
    #pragma unroll 8
    for (int t = 0; t < DD; ++t) {
        float a = aW1[t * HATTN + c];
        wq  = fmaf(srow[0][t], a, wq);
        wk  = fmaf(srow[1][t], a, wk);
        w12 = fmaf(srow[2][t], a, w12);
    }
    g_Wqa[r * HATTN + c] = wq;
    g_Wka[r * HATTN + c] = wk;
    g_W12[r * HATTN + c] = w12;
    if (r == 0) {
        float b = ab1[c];
        for (int t = 0; t < DD; ++t) b = fmaf(pb2[t], aW1[t * HATTN + c], b);
        g_bqa[c] = b;
    }
}

// ---------------------------------------------------------------------------
// prepF: pack W12 / aW2 / pW2 into fp16 B-fragment images (9216 entries).
// ---------------------------------------------------------------------------
__global__ void prepF(const float* __restrict__ aW2, const float* __restrict__ pW2)
{
    const int e = blockIdx.x * 256 + threadIdx.x;
    const int lane = e & 31, gg = lane >> 2, tg = lane & 3;
    if (e < 4096) {                                      // W12, K=64, N=256
        const int kk = e >> 10, nt = (e >> 5) & 31;
        const int k0 = 16 * kk + 2 * tg, n0 = 8 * nt + gg;
        uint2 v;
        v.x = fp2h2(g_W12[(k0    ) * HATTN + n0], g_W12[(k0 + 1) * HATTN + n0]);
        v.y = fp2h2(g_W12[(k0 + 8) * HATTN + n0], g_W12[(k0 + 9) * HATTN + n0]);
        g_W1f[e] = v;
    } else if (e < 8192) {                               // aW2, K=256, N=64
        const int l = e - 4096;
        const int kk = l >> 8, nt = (l >> 5) & 7;
        const int k0 = 16 * kk + 2 * tg, n0 = 8 * nt + gg;
        uint2 v;
        v.x = fp2h2(aW2[(k0    ) * DD + n0], aW2[(k0 + 1) * DD + n0]);
        v.y = fp2h2(aW2[(k0 + 8) * DD + n0], aW2[(k0 + 9) * DD + n0]);
        g_aW2f[l] = v;
    } else if (e < 9216) {                               // pW2, K=64, N=64
        const int l = e - 8192;
        const int kk = l >> 8, nt = (l >> 5) & 7;
        const int k0 = 16 * kk + 2 * tg, n0 = 8 * nt + gg;
        uint2 v;
        v.x = fp2h2(pW2[(k0    ) * DD + n0], pW2[(k0 + 1) * DD + n0]);
        v.y = fp2h2(pW2[(k0 + 8) * DD + n0], pW2[(k0 + 9) * DD + n0]);
        g_pW2f[l] = v;
    }
}

// ---------------------------------------------------------------------------
// prep2: qa (fp32), d (fp16), ka/vs in fragment-ordered fp16. grid N x 256.
// ---------------------------------------------------------------------------
__global__ void prep2(const float* __restrict__ x, const float* __restrict__ pos,
                      const float* __restrict__ Wv, const float* __restrict__ pW1,
                      int N)
{
    __shared__ float sx[DD];
    const int n = blockIdx.x, c = threadIdx.x;
    if (c < DD) sx[c] = x[n * DD + c];
    __syncthreads();
    float aq = g_bqa[c], ak = 0.f;
    #pragma unroll 8
    for (int t = 0; t < DD; ++t) {
        float xv = sx[t];
        aq = fmaf(xv, g_Wqa[t * HATTN + c], aq);
        ak = fmaf(xv, g_Wka[t * HATTN + c], ak);
    }
    g_qa[n * HATTN + c] = aq;
    const int rb = n >> 4, rr = n & 15, gg = rr & 7, hi = rr >> 3;
    {
        const int chk = c >> 5, nt = (c >> 3) & 3, tg = (c & 7) >> 1, lo = c & 1;
        const int ent = ((rb * 8 + chk) * 4 + nt) * 32 + (gg * 4 + tg);
        reinterpret_cast<__half*>(g_kaf)[ent * 4 + hi * 2 + lo] = __float2half(ak);
    }
    if (c < DD) {
        float av = 0.f;
        for (int t = 0; t < DD; ++t) av = fmaf(sx[t], Wv[t * DD + c], av);
        const int nt2 = c >> 3, tg = (c & 7) >> 1, lo = c & 1;
        const int ent = (rb * 8 + nt2) * 32 + (gg * 4 + tg);
        reinterpret_cast<__half*>(g_vsf)[ent * 4 + hi * 2 + lo] = __float2half(av);
        g_d16[n * DD + c] = __float2half(fmaf(pos[2 * n], pW1[c],
                                              pos[2 * n + 1] * pW1[DD + c]));
    }
}

// ---------------------------------------------------------------------------
// main: CTA (256 thr, 8 warps) per query; warp covers 32 rows (mt=2) of each
// 256-row j-tile; fp16 C for GEMM1/GEMM3 keeps regs <=128 -> 2 CTAs/SM.
// ---------------------------------------------------------------------------
#define OFF_W1F  0
#define OFF_AW2F 32768
#define OFF_PW2F 65536
#define OFF_QA   73728
#define OFF_QAH  74752
#define OFF_CI   75264
#define OFF_REDS 75520
#define OFF_REDA 77568
#define SMEM_SZ  79616

__global__ void __launch_bounds__(256, 2)
pt_main(const float* __restrict__ pos, const float* __restrict__ pW1,
        const float* __restrict__ pb1, const float* __restrict__ pb2,
        float* __restrict__ out, int N)
{
    extern __shared__ char smem[];
    uint2*    sW1f  = (uint2*)(smem + OFF_W1F);
    uint2*    sAW2f = (uint2*)(smem + OFF_AW2F);
    uint2*    sPW2f = (uint2*)(smem + OFF_PW2F);
    float*    sQa   = (float*)(smem + OFF_QA);
    __half2*  sQah  = (__half2*)(smem + OFF_QAH);
    float*    sCi   = (float*)(smem + OFF_CI);
    float*    sRedS = (float*)(smem + OFF_REDS);
    float*    sRedA = (float*)(smem + OFF_REDA);

    const int tid  = threadIdx.x;
    const int i    = blockIdx.x;
    const int w    = tid >> 5, lane = tid & 31;
    const int g    = lane >> 2, tig = lane & 3;

    {   // stage weight fragment images
        uint4* d1 = (uint4*)sW1f;   const uint4* s1 = (const uint4*)g_W1f;
        uint4* d2 = (uint4*)sAW2f;  const uint4* s2 = (const uint4*)g_aW2f;
        uint4* d3 = (uint4*)sPW2f;  const uint4* s3 = (const uint4*)g_pW2f;
        for (int k = tid; k < 2048; k += 256) { d1[k] = s1[k]; d2[k] = s2[k]; }
        for (int k = tid; k < 512;  k += 256) d3[k] = s3[k];
    }
    sQa[tid] = g_qa[i * HATTN + tid];
    const float posIx = pos[2 * i], posIy = pos[2 * i + 1];
    if (tid < 64)
        sCi[tid] = fmaf(posIx, pW1[tid], fmaf(posIy, pW1[DD + tid], pb1[tid]));
    sRedS[tid] = 0.f; sRedS[tid + 256] = 0.f;
    sRedA[tid] = 0.f; sRedA[tid + 256] = 0.f;
    __syncthreads();
    if (tid < 128) sQah[tid] = __floats2half2_rn(sQa[2 * tid], sQa[2 * tid + 1]);
    __syncthreads();

    const __half2 hzero = __float2half2_rn(0.f);
    const int ntile = N >> 8;                 // 256 rows per tile; warp = 32 rows
    for (int jt = 0; jt < ntile; ++jt) {
        const int rb0 = jt * 16 + w * 2;      // two 16-row blocks per warp

        // ---- A fragments: U = relu(ci - d_j), K=64, mt=2 ----
        unsigned Af[2][4][4];
        #pragma unroll
        for (int kk = 0; kk < 4; ++kk) {
            const float c0 = sCi[16 * kk + 2 * tig];
            const float c1 = sCi[16 * kk + 2 * tig + 1];
            const float c2 = sCi[16 * kk + 2 * tig + 8];
            const float c3 = sCi[16 * kk + 2 * tig + 9];
            #pragma unroll
            for (int mt = 0; mt < 2; ++mt) {
                const int rlo = (rb0 + mt) * 16 + g, rhi = rlo + 8;
                float2 dl0 = __half22float2(*(const __half2*)&g_d16[rlo * DD + 16 * kk + 2 * tig]);
                float2 dl1 = __half22float2(*(const __half2*)&g_d16[rlo * DD + 16 * kk + 2 * tig + 8]);
                float2 dh0 = __half22float2(*(const __half2*)&g_d16[rhi * DD + 16 * kk + 2 * tig]);
                float2 dh1 = __half22float2(*(const __half2*)&g_d16[rhi * DD + 16 * kk + 2 * tig + 8]);
                Af[mt][kk][0] = fp2h2(fmaxf(c0 - dl0.x, 0.f), fmaxf(c1 - dl0.y, 0.f));
                Af[mt][kk][1] = fp2h2(fmaxf(c0 - dh0.x, 0.f), fmaxf(c1 - dh0.y, 0.f));
                Af[mt][kk][2] = fp2h2(fmaxf(c2 - dl1.x, 0.f), fmaxf(c3 - dl1.y, 0.f));
                Af[mt][kk][3] = fp2h2(fmaxf(c2 - dh1.x, 0.f), fmaxf(c3 - dh1.y, 0.f));
            }
        }

        float sc[2][8][4];
        #pragma unroll
        for (int mt = 0; mt < 2; ++mt)
            #pragma unroll
            for (int a = 0; a < 8; ++a)
                { sc[mt][a][0]=0.f; sc[mt][a][1]=0.f; sc[mt][a][2]=0.f; sc[mt][a][3]=0.f; }

        #pragma unroll 1
        for (int chk = 0; chk < 8; ++chk) {              // 32 attn channels / chunk
            // GEMM1: P = U @ W12 (K=64), fp16 C, both m-tiles share B
            unsigned pa[2][4][2];
            #pragma unroll
            for (int mt = 0; mt < 2; ++mt)
                #pragma unroll
                for (int a = 0; a < 4; ++a) { pa[mt][a][0] = 0u; pa[mt][a][1] = 0u; }
            #pragma unroll
            for (int kk = 0; kk < 4; ++kk) {
                uint2 b0 = sW1f[((kk * 32) + (chk * 4 + 0)) * 32 + lane];
                uint2 b1 = sW1f[((kk * 32) + (chk * 4 + 1)) * 32 + lane];
                uint2 b2 = sW1f[((kk * 32) + (chk * 4 + 2)) * 32 + lane];
                uint2 b3 = sW1f[((kk * 32) + (chk * 4 + 3)) * 32 + lane];
                #pragma unroll
                for (int mt = 0; mt < 2; ++mt) {
                    mma16h(pa[mt][0], Af[mt][kk], b0);
                    mma16h(pa[mt][1], Af[mt][kk], b1);
                    mma16h(pa[mt][2], Af[mt][kk], b2);
                    mma16h(pa[mt][3], Af[mt][kk], b3);
                }
            }
            // epilogue: v = relu(pa + qa - ka); fp16 D layout == GEMM2 A layout
            unsigned a2[2][2][4];
            #pragma unroll
            for (int nt = 0; nt < 4; ++nt) {
                const __half2 qa2 = sQah[chk * 16 + nt * 4 + tig];
                #pragma unroll
                for (int mt = 0; mt < 2; ++mt) {
                    uint2 kafr = __ldg(&g_kaf[(((rb0 + mt) * 8 + chk) * 4 + nt) * 32 + lane]);
                    __half2 qk0 = __hsub2(qa2, *reinterpret_cast<__half2*>(&kafr.x));
                    __half2 qk1 = __hsub2(qa2, *reinterpret_cast<__half2*>(&kafr.y));
                    __half2 r0  = __hmax2(__hadd2(*reinterpret_cast<__half2*>(&pa[mt][nt][0]), qk0), hzero);
                    __half2 r1  = __hmax2(__hadd2(*reinterpret_cast<__half2*>(&pa[mt][nt][1]), qk1), hzero);
                    const int kk2 = nt >> 1, sl = (nt & 1) << 1;
                    a2[mt][kk2][sl]     = *reinterpret_cast<unsigned*>(&r0);
                    a2[mt][kk2][sl + 1] = *reinterpret_cast<unsigned*>(&r1);
                }
            }
            // GEMM2 partial: sim += P' @ aW2 (K=32 this chunk), fp32 C, shared B
            #pragma unroll
            for (int kk2 = 0; kk2 < 2; ++kk2)
                #pragma unroll
                for (int nt2 = 0; nt2 < 8; ++nt2) {
                    uint2 b = sAW2f[(((chk * 2 + kk2) * 8) + nt2) * 32 + lane];
                    mma16(sc[0][nt2], a2[0][kk2], b);
                    mma16(sc[1][nt2], a2[1][kk2], b);
                }
        }

        // GEMM3 (fp16 C) + exp + accumulate + per-mt reduce
        #pragma unroll 1
        for (int mt = 0; mt < 2; ++mt) {
            const int rb = rb0 + mt;
            unsigned ra[8][2];
            #pragma unroll
            for (int a = 0; a < 8; ++a) { ra[a][0] = 0u; ra[a][1] = 0u; }
            #pragma unroll
            for (int kk = 0; kk < 4; ++kk)
                #pragma unroll
                for (int nt = 0; nt < 8; ++nt) {
                    uint2 b = sPW2f[(kk * 8 + nt) * 32 + lane];
                    mma16h(ra[nt], Af[mt][kk], b);
                }
            float Sr[16], Ar[16];
            #pragma unroll
            for (int nt2 = 0; nt2 < 8; ++nt2) {
                uint2 vsfr = __ldg(&g_vsf[(rb * 8 + nt2) * 32 + lane]);
                __half2 vv0 = __hadd2(*reinterpret_cast<__half2*>(&vsfr.x),
                                      *reinterpret_cast<__half2*>(&ra[nt2][0]));
                __half2 vv1 = __hadd2(*reinterpret_cast<__half2*>(&vsfr.y),
                                      *reinterpret_cast<__half2*>(&ra[nt2][1]));
                float2 vl = __half22float2(vv0);
                float2 vh = __half22float2(vv1);
                float e0 = __expf(sc[mt][nt2][0]);
                float e1 = __expf(sc[mt][nt2][1]);
                float e2 = __expf(sc[mt][nt2][2]);
                float e3 = __expf(sc[mt][nt2][3]);
                Sr[nt2 * 2 + 0] = e0 + e2;
                Sr[nt2 * 2 + 1] = e1 + e3;
                Ar[nt2 * 2 + 0] = e0 * vl.x + e2 * vh.x;
                Ar[nt2 * 2 + 1] = e1 * vl.y + e3 * vh.y;
            }
            #pragma unroll
            for (int q = 0; q < 16; ++q) {
                float s = Sr[q], a = Ar[q];
                s += __shfl_xor_sync(0xffffffffu, s, 4);
                a += __shfl_xor_sync(0xffffffffu, a, 4);
                s += __shfl_xor_sync(0xffffffffu, s, 8);
                a += __shfl_xor_sync(0xffffffffu, a, 8);
                s += __shfl_xor_sync(0xffffffffu, s, 16);
                a += __shfl_xor_sync(0xffffffffu, a, 16);
                Sr[q] = s; Ar[q] = a;
            }
            if (lane < 4) {
                #pragma unroll
                for (int nt2 = 0; nt2 < 8; ++nt2) {
                    const int d0 = w * DD + nt2 * 8 + 2 * lane;
                    sRedS[d0]     += Sr[nt2 * 2 + 0];
                    sRedS[d0 + 1] += Sr[nt2 * 2 + 1];
                    sRedA[d0]     += Ar[nt2 * 2 + 0];
                    sRedA[d0 + 1] += Ar[nt2 * 2 + 1];
                }
            }
        }
    }

    __syncthreads();
    if (tid < DD) {
        float s = 0.f, a = 0.f;
        #pragma unroll
        for (int q = 0; q < 8; ++q) { s += sRedS[q * DD + tid]; a += sRedA[q * DD + tid]; }
        out[i * DD + tid] = a / s + pb2[tid];
    }
}

// ---------------------------------------------------------------------------
extern "C" void kernel_launch(void* const* d_in, const int* in_sizes, int n_in,
                              void* d_out, int out_size)
{
    const float* x   = (const float*)d_in[0];
    const float* pos = (const float*)d_in[1];
    const float* Wq  = (const float*)d_in[2];
    const float* Wk  = (const float*)d_in[3];
    const float* Wv  = (const float*)d_in[4];
    const float* pW1 = (const float*)d_in[5];
    const float* pb1 = (const float*)d_in[6];
    const float* pW2 = (const float*)d_in[7];
    const float* pb2 = (const float*)d_in[8];
    const float* aW1 = (const float*)d_in[9];
    const float* ab1 = (const float*)d_in[10];
    const float* aW2 = (const float*)d_in[11];
    // d_in[12] = ab2: constant over j -> softmax-invariant -> unused.

    const int N = in_sizes[0] / DD;   // B = 1
    float* out  = (float*)d_out;

    prep1<<<DD, 256>>>(Wq, Wk, pW2, aW1, ab1, pb2);
    prepF<<<36, 256>>>(aW2, pW2);
    prep2<<<N, 256>>>(x, pos, Wv, pW1, N);

    cudaFuncSetAttribute((const void*)pt_main,
                         cudaFuncAttributeMaxDynamicSharedMemorySize, SMEM_SZ);
    pt_main<<<N, 256, SMEM_SZ>>>(pos, pW1, pb1, pb2, out, N);
}

// round 11
// speedup vs baseline: 1.6547x; 1.6292x over previous
#include <cuda_runtime.h>
#include <cuda_fp16.h>
#include <cstdint>

#define DD    64
#define HATTN 256
#define NMAX  2048

// ---------------- device-global scratch (no allocs allowed) ----------------
__device__ float  g_Wqa[DD * HATTN];
__device__ float  g_Wka[DD * HATTN];
__device__ float  g_W12[DD * HATTN];      // (pW2@aW1)[h][c]
__device__ float  g_bqa[HATTN];
__device__ float  g_qa [NMAX * HATTN];    // fp32
__device__ __half g_d16[NMAX * DD];       // d_j = pos_j @ pW1 (no bias)
// fragment-ordered fp16 data images (one coalesced LDG.64 per fragment):
__device__ uint2  g_kaf[(NMAX / 16) * 8 * 4 * 32];  // ka: [rb][chk][nt][lane]
__device__ uint2  g_vsf[(NMAX / 16) * 8 * 32];      // vs=x@Wv: [rb][nt2][lane]
// fp16 B-fragment weight images: uint2 = {half2(k0,k0+1), half2(k0+8,k0+9)} at col n0
__device__ uint2  g_W1f [4096];           // W12 : K=64 [kk=4][ntg=32][lane=32]
__device__ uint2  g_aW2f[4096];           // aW2 : K=256 [kk=16][nt=8][lane=32]
__device__ uint2  g_pW2f[1024];           // pW2 : K=64 [kk=4][nt=8][lane=32]

__device__ __forceinline__ unsigned fp2h2(float a, float b) {
    __half2 h = __floats2half2_rn(a, b);
    return *reinterpret_cast<unsigned*>(&h);
}
__device__ __forceinline__ void mma16(float* c, const unsigned* a, uint2 b) {
    asm volatile("mma.sync.aligned.m16n8k16.row.col.f32.f16.f16.f32 "
                 "{%0,%1,%2,%3}, {%4,%5,%6,%7}, {%8,%9}, {%0,%1,%2,%3};"
                 : "+f"(c[0]), "+f"(c[1]), "+f"(c[2]), "+f"(c[3])
                 : "r"(a[0]), "r"(a[1]), "r"(a[2]), "r"(a[3]), "r"(b.x), "r"(b.y));
}
__device__ __forceinline__ void mma16h(unsigned* d, const unsigned* a, uint2 b) {
    asm volatile("mma.sync.aligned.m16n8k16.row.col.f16.f16.f16.f16 "
                 "{%0,%1}, {%2,%3,%4,%5}, {%6,%7}, {%0,%1};"
                 : "+r"(d[0]), "+r"(d[1])
                 : "r"(a[0]), "r"(a[1]), "r"(a[2]), "r"(a[3]), "r"(b.x), "r"(b.y));
}

// ---------------------------------------------------------------------------
// prep1: weight folds W12 = pW2@aW1, Wqa = Wq@aW1, Wka = Wk@aW1, bqa.
// ---------------------------------------------------------------------------
__global__ void prep1(const float* __restrict__ Wq, const float* __restrict__ Wk,
                      const float* __restrict__ pW2, const float* __restrict__ aW1,
                      const float* __restrict__ ab1, const float* __restrict__ pb2)
{
    __shared__ float srow[3][DD];
    const int r = blockIdx.x, c = threadIdx.x;
    if (c < 64)       srow[0][c]       = Wq [r * DD + c];
    else if (c < 128) srow[1][c - 64]  = Wk [r * DD + (c - 64)];
    else if (c < 192) srow[2][c - 128] = pW2[r * DD + (c - 128)];
    __syncthreads();
    float wq = 0.f, wk = 0.f, w12 = 0.f;
    #pragma unroll 8
    for (int t = 0; t < DD; ++t) {
        float a = aW1[t * HATTN + c];
        wq  = fmaf(srow[0][t], a, wq);
        wk  = fmaf(srow[1][t], a, wk);
        w12 = fmaf(srow[2][t], a, w12);
    }
    g_Wqa[r * HATTN + c] = wq;
    g_Wka[r * HATTN + c] = wk;
    g_W12[r * HATTN + c] = w12;
    if (r == 0) {
        float b = ab1[c];
        for (int t = 0; t < DD; ++t) b = fmaf(pb2[t], aW1[t * HATTN + c], b);
        g_bqa[c] = b;
    }
}

// ---------------------------------------------------------------------------
// prepF: pack W12 / aW2 / pW2 into fp16 B-fragment images (9216 entries).
// ---------------------------------------------------------------------------
__global__ void prepF(const float* __restrict__ aW2, const float* __restrict__ pW2)
{
    const int e = blockIdx.x * 256 + threadIdx.x;
    const int lane = e & 31, gg = lane >> 2, tg = lane & 3;
    if (e < 4096) {                                      // W12, K=64, N=256
        const int kk = e >> 10, nt = (e >> 5) & 31;
        const int k0 = 16 * kk + 2 * tg, n0 = 8 * nt + gg;
        uint2 v;
        v.x = fp2h2(g_W12[(k0    ) * HATTN + n0], g_W12[(k0 + 1) * HATTN + n0]);
        v.y = fp2h2(g_W12[(k0 + 8) * HATTN + n0], g_W12[(k0 + 9) * HATTN + n0]);
        g_W1f[e] = v;
    } else if (e < 8192) {                               // aW2, K=256, N=64
        const int l = e - 4096;
        const int kk = l >> 8, nt = (l >> 5) & 7;
        const int k0 = 16 * kk + 2 * tg, n0 = 8 * nt + gg;
        uint2 v;
        v.x = fp2h2(aW2[(k0    ) * DD + n0], aW2[(k0 + 1) * DD + n0]);
        v.y = fp2h2(aW2[(k0 + 8) * DD + n0], aW2[(k0 + 9) * DD + n0]);
        g_aW2f[l] = v;
    } else if (e < 9216) {                               // pW2, K=64, N=64
        const int l = e - 8192;
        const int kk = l >> 8, nt = (l >> 5) & 7;
        const int k0 = 16 * kk + 2 * tg, n0 = 8 * nt + gg;
        uint2 v;
        v.x = fp2h2(pW2[(k0    ) * DD + n0], pW2[(k0 + 1) * DD + n0]);
        v.y = fp2h2(pW2[(k0 + 8) * DD + n0], pW2[(k0 + 9) * DD + n0]);
        g_pW2f[l] = v;
    }
}

// ---------------------------------------------------------------------------
// prep2: qa (fp32), d (fp16), ka/vs in fragment-ordered fp16. grid N x 256.
// ---------------------------------------------------------------------------
__global__ void prep2(const float* __restrict__ x, const float* __restrict__ pos,
                      const float* __restrict__ Wv, const float* __restrict__ pW1,
                      int N)
{
    __shared__ float sx[DD];
    const int n = blockIdx.x, c = threadIdx.x;
    if (c < DD) sx[c] = x[n * DD + c];
    __syncthreads();
    float aq = g_bqa[c], ak = 0.f;
    #pragma unroll 8
    for (int t = 0; t < DD; ++t) {
        float xv = sx[t];
        aq = fmaf(xv, g_Wqa[t * HATTN + c], aq);
        ak = fmaf(xv, g_Wka[t * HATTN + c], ak);
    }
    g_qa[n * HATTN + c] = aq;
    const int rb = n >> 4, rr = n & 15, gg = rr & 7, hi = rr >> 3;
    {
        const int chk = c >> 5, nt = (c >> 3) & 3, tg = (c & 7) >> 1, lo = c & 1;
        const int ent = ((rb * 8 + chk) * 4 + nt) * 32 + (gg * 4 + tg);
        reinterpret_cast<__half*>(g_kaf)[ent * 4 + hi * 2 + lo] = __float2half(ak);
    }
    if (c < DD) {
        float av = 0.f;
        for (int t = 0; t < DD; ++t) av = fmaf(sx[t], Wv[t * DD + c], av);
        const int nt2 = c >> 3, tg = (c & 7) >> 1, lo = c & 1;
        const int ent = (rb * 8 + nt2) * 32 + (gg * 4 + tg);
        reinterpret_cast<__half*>(g_vsf)[ent * 4 + hi * 2 + lo] = __float2half(av);
        g_d16[n * DD + c] = __float2half(fmaf(pos[2 * n], pW1[c],
                                              pos[2 * n + 1] * pW1[DD + c]));
    }
}

// ---------------------------------------------------------------------------
// main: round-7 frame (one CTA/query, 8 warps x 16 rows, 2 CTAs/SM) +
// fp16-C GEMM1/GEMM3 (reg slack) + ka double-buffer across chunks.
// ---------------------------------------------------------------------------
#define OFF_W1F  0
#define OFF_AW2F 32768
#define OFF_PW2F 65536
#define OFF_QA   73728
#define OFF_QAH  74752
#define OFF_CI   75264
#define OFF_REDS 75520
#define OFF_REDA 77568
#define SMEM_SZ  79616

__global__ void __launch_bounds__(256, 2)
pt_main(const float* __restrict__ pos, const float* __restrict__ pW1,
        const float* __restrict__ pb1, const float* __restrict__ pb2,
        float* __restrict__ out, int N)
{
    extern __shared__ char smem[];
    uint2*   sW1f  = (uint2*)(smem + OFF_W1F);
    uint2*   sAW2f = (uint2*)(smem + OFF_AW2F);
    uint2*   sPW2f = (uint2*)(smem + OFF_PW2F);
    float*   sQa   = (float*)(smem + OFF_QA);
    __half2* sQah  = (__half2*)(smem + OFF_QAH);
    float*   sCi   = (float*)(smem + OFF_CI);
    float*   sRedS = (float*)(smem + OFF_REDS);
    float*   sRedA = (float*)(smem + OFF_REDA);

    const int tid  = threadIdx.x;
    const int i    = blockIdx.x;
    const int w    = tid >> 5, lane = tid & 31;
    const int g    = lane >> 2, tig = lane & 3;

    {   // stage weight fragment images
        uint4* d1 = (uint4*)sW1f;   const uint4* s1 = (const uint4*)g_W1f;
        uint4* d2 = (uint4*)sAW2f;  const uint4* s2 = (const uint4*)g_aW2f;
        uint4* d3 = (uint4*)sPW2f;  const uint4* s3 = (const uint4*)g_pW2f;
        for (int k = tid; k < 2048; k += 256) { d1[k] = s1[k]; d2[k] = s2[k]; }
        for (int k = tid; k < 512;  k += 256) d3[k] = s3[k];
    }
    sQa[tid] = g_qa[i * HATTN + tid];
    const float posIx = pos[2 * i], posIy = pos[2 * i + 1];
    if (tid < 64)
        sCi[tid] = fmaf(posIx, pW1[tid], fmaf(posIy, pW1[DD + tid], pb1[tid]));
    sRedS[tid] = 0.f; sRedS[tid + 256] = 0.f;
    sRedA[tid] = 0.f; sRedA[tid + 256] = 0.f;
    __syncthreads();
    if (tid < 128) sQah[tid] = __floats2half2_rn(sQa[2 * tid], sQa[2 * tid + 1]);
    __syncthreads();

    const __half2 hzero = __float2half2_rn(0.f);
    const int ntile = N >> 7;                 // 128 rows per tile; warp = 16 rows
    for (int jt = 0; jt < ntile; ++jt) {
        const int rb  = jt * 8 + w;           // this warp's 16-row block
        const int rlo = rb * 16 + g, rhi = rlo + 8;
        const uint2* kaRow = &g_kaf[rb * 8 * 4 * 32];
        const uint2* vsRow = &g_vsf[rb * 8 * 32];

        // ---- A fragments: U = relu(ci - d_j), K=64 ----
        unsigned Af[4][4];
        #pragma unroll
        for (int kk = 0; kk < 4; ++kk) {
            const float c0 = sCi[16 * kk + 2 * tig];
            const float c1 = sCi[16 * kk + 2 * tig + 1];
            const float c2 = sCi[16 * kk + 2 * tig + 8];
            const float c3 = sCi[16 * kk + 2 * tig + 9];
            float2 dl0 = __half22float2(*(const __half2*)&g_d16[rlo * DD + 16 * kk + 2 * tig]);
            float2 dl1 = __half22float2(*(const __half2*)&g_d16[rlo * DD + 16 * kk + 2 * tig + 8]);
            float2 dh0 = __half22float2(*(const __half2*)&g_d16[rhi * DD + 16 * kk + 2 * tig]);
            float2 dh1 = __half22float2(*(const __half2*)&g_d16[rhi * DD + 16 * kk + 2 * tig + 8]);
            Af[kk][0] = fp2h2(fmaxf(c0 - dl0.x, 0.f), fmaxf(c1 - dl0.y, 0.f));
            Af[kk][1] = fp2h2(fmaxf(c0 - dh0.x, 0.f), fmaxf(c1 - dh0.y, 0.f));
            Af[kk][2] = fp2h2(fmaxf(c2 - dl1.x, 0.f), fmaxf(c3 - dl1.y, 0.f));
            Af[kk][3] = fp2h2(fmaxf(c2 - dh1.x, 0.f), fmaxf(c3 - dh1.y, 0.f));
        }

        float sc[8][4];
        #pragma unroll
        for (int a = 0; a < 8; ++a)
            { sc[a][0]=0.f; sc[a][1]=0.f; sc[a][2]=0.f; sc[a][3]=0.f; }

        // ka double-buffer: chunk 0 preloaded; chunk c+1 issued at top of c
        uint2 kac[4];
        #pragma unroll
        for (int nt = 0; nt < 4; ++nt)
            kac[nt] = __ldg(&kaRow[nt * 32 + lane]);

        #pragma unroll 1
        for (int chk = 0; chk < 8; ++chk) {              // 32 attn channels / chunk
            uint2 kan[4];
            const int cn = (chk + 1) & 7;                // wrap: harmless reload at tail
            #pragma unroll
            for (int nt = 0; nt < 4; ++nt)
                kan[nt] = __ldg(&kaRow[(cn * 4 + nt) * 32 + lane]);

            // GEMM1: P = U @ W12 (K=64), fp16 C
            unsigned pa[4][2];
            #pragma unroll
            for (int a = 0; a < 4; ++a) { pa[a][0] = 0u; pa[a][1] = 0u; }
            #pragma unroll
            for (int kk = 0; kk < 4; ++kk) {
                uint2 b0 = sW1f[((kk * 32) + (chk * 4 + 0)) * 32 + lane];
                uint2 b1 = sW1f[((kk * 32) + (chk * 4 + 1)) * 32 + lane];
                uint2 b2 = sW1f[((kk * 32) + (chk * 4 + 2)) * 32 + lane];
                uint2 b3 = sW1f[((kk * 32) + (chk * 4 + 3)) * 32 + lane];
                mma16h(pa[0], Af[kk], b0);
                mma16h(pa[1], Af[kk], b1);
                mma16h(pa[2], Af[kk], b2);
                mma16h(pa[3], Af[kk], b3);
            }
            // epilogue: v = relu(pa + qa - ka); fp16 D layout == GEMM2 A layout
            unsigned a2[2][4];
            #pragma unroll
            for (int nt = 0; nt < 4; ++nt) {
                const __half2 qa2 = sQah[chk * 16 + nt * 4 + tig];
                __half2 qk0 = __hsub2(qa2, *reinterpret_cast<__half2*>(&kac[nt].x));
                __half2 qk1 = __hsub2(qa2, *reinterpret_cast<__half2*>(&kac[nt].y));
                __half2 r0  = __hmax2(__hadd2(*reinterpret_cast<__half2*>(&pa[nt][0]), qk0), hzero);
                __half2 r1  = __hmax2(__hadd2(*reinterpret_cast<__half2*>(&pa[nt][1]), qk1), hzero);
                const int kk2 = nt >> 1, sl = (nt & 1) << 1;
                a2[kk2][sl]     = *reinterpret_cast<unsigned*>(&r0);
                a2[kk2][sl + 1] = *reinterpret_cast<unsigned*>(&r1);
            }
            // GEMM2 partial: sim += P' @ aW2 (K=32 this chunk), fp32 C
            #pragma unroll
            for (int kk2 = 0; kk2 < 2; ++kk2)
                #pragma unroll
                for (int nt2 = 0; nt2 < 8; ++nt2) {
                    uint2 b = sAW2f[(((chk * 2 + kk2) * 8) + nt2) * 32 + lane];
                    mma16(sc[nt2], a2[kk2], b);
                }
            #pragma unroll
            for (int nt = 0; nt < 4; ++nt) kac[nt] = kan[nt];
        }

        // vs fragments (coalesced LDG.64; overlap GEMM3)
        uint2 vsfr[8];
        #pragma unroll
        for (int nt2 = 0; nt2 < 8; ++nt2)
            vsfr[nt2] = __ldg(&vsRow[nt2 * 32 + lane]);

        // GEMM3: rpe = U @ pW2 (K=64), fp16 C
        unsigned ra[8][2];
        #pragma unroll
        for (int a = 0; a < 8; ++a) { ra[a][0] = 0u; ra[a][1] = 0u; }
        #pragma unroll
        for (int kk = 0; kk < 4; ++kk)
            #pragma unroll
            for (int nt = 0; nt < 8; ++nt) {
                uint2 b = sPW2f[(kk * 8 + nt) * 32 + lane];
                mma16h(ra[nt], Af[kk], b);
            }

        // exp + weighted accumulation, then per-tile reduce over rows
        float Sr[16], Ar[16];
        #pragma unroll
        for (int nt2 = 0; nt2 < 8; ++nt2) {
            __half2 vv0 = __hadd2(*reinterpret_cast<__half2*>(&vsfr[nt2].x),
                                  *reinterpret_cast<__half2*>(&ra[nt2][0]));
            __half2 vv1 = __hadd2(*reinterpret_cast<__half2*>(&vsfr[nt2].y),
                                  *reinterpret_cast<__half2*>(&ra[nt2][1]));
            float2 vl = __half22float2(vv0);
            float2 vh = __half22float2(vv1);
            float e0 = __expf(sc[nt2][0]);
            float e1 = __expf(sc[nt2][1]);
            float e2 = __expf(sc[nt2][2]);
            float e3 = __expf(sc[nt2][3]);
            Sr[nt2 * 2 + 0] = e0 + e2;
            Sr[nt2 * 2 + 1] = e1 + e3;
            Ar[nt2 * 2 + 0] = e0 * vl.x + e2 * vh.x;
            Ar[nt2 * 2 + 1] = e1 * vl.y + e3 * vh.y;
        }
        #pragma unroll
        for (int q = 0; q < 16; ++q) {
            float s = Sr[q], a = Ar[q];
            s += __shfl_xor_sync(0xffffffffu, s, 4);
            a += __shfl_xor_sync(0xffffffffu, a, 4);
            s += __shfl_xor_sync(0xffffffffu, s, 8);
            a += __shfl_xor_sync(0xffffffffu, a, 8);
            s += __shfl_xor_sync(0xffffffffu, s, 16);
            a += __shfl_xor_sync(0xffffffffu, a, 16);
            Sr[q] = s; Ar[q] = a;
        }
        if (lane < 4) {
            #pragma unroll
            for (int nt2 = 0; nt2 < 8; ++nt2) {
                const int d0 = w * DD + nt2 * 8 + 2 * lane;
                sRedS[d0]     += Sr[nt2 * 2 + 0];
                sRedS[d0 + 1] += Sr[nt2 * 2 + 1];
                sRedA[d0]     += Ar[nt2 * 2 + 0];
                sRedA[d0 + 1] += Ar[nt2 * 2 + 1];
            }
        }
    }

    __syncthreads();
    if (tid < DD) {
        float s = 0.f, a = 0.f;
        #pragma unroll
        for (int q = 0; q < 8; ++q) { s += sRedS[q * DD + tid]; a += sRedA[q * DD + tid]; }
        out[i * DD + tid] = a / s + pb2[tid];
    }
}

// ---------------------------------------------------------------------------
extern "C" void kernel_launch(void* const* d_in, const int* in_sizes, int n_in,
                              void* d_out, int out_size)
{
    const float* x   = (const float*)d_in[0];
    const float* pos = (const float*)d_in[1];
    const float* Wq  = (const float*)d_in[2];
    const float* Wk  = (const float*)d_in[3];
    const float* Wv  = (const float*)d_in[4];
    const float* pW1 = (const float*)d_in[5];
    const float* pb1 = (const float*)d_in[6];
    const float* pW2 = (const float*)d_in[7];
    const float* pb2 = (const float*)d_in[8];
    const float* aW1 = (const float*)d_in[9];
    const float* ab1 = (const float*)d_in[10];
    const float* aW2 = (const float*)d_in[11];
    // d_in[12] = ab2: constant over j -> softmax-invariant -> unused.

    const int N = in_sizes[0] / DD;   // B = 1
    float* out  = (float*)d_out;

    prep1<<<DD, 256>>>(Wq, Wk, pW2, aW1, ab1, pb2);
    prepF<<<36, 256>>>(aW2, pW2);
    prep2<<<N, 256>>>(x, pos, Wv, pW1, N);

    cudaFuncSetAttribute((const void*)pt_main,
                         cudaFuncAttributeMaxDynamicSharedMemorySize, SMEM_SZ);
    pt_main<<<N, 256, SMEM_SZ>>>(pos, pW1, pb1, pb2, out, N);
}

// round 14
// speedup vs baseline: 1.7965x; 1.0857x over previous
#include <cuda_runtime.h>
#include <cuda_fp16.h>
#include <cstdint>

#define DD    64
#define HATTN 256
#define NMAX  2048

// ---------------- device-global scratch (no allocs allowed) ----------------
__device__ float  g_Wqa[DD * HATTN];
__device__ float  g_Wka[DD * HATTN];
__device__ float  g_W12[DD * HATTN];      // (pW2@aW1)[h][c]
__device__ float  g_bqa[HATTN];
__device__ float  g_qa [NMAX * HATTN];    // fp32
__device__ float  g_part[2 * NMAX * 128]; // per-(i,half): [0:64) S, [64:128) A
// fragment-ordered fp16 data images (coalesced LDG per fragment):
__device__ uint4  g_dff[(NMAX / 16) * 4 * 32];      // d = pos@pW1: [rb][kk][lane]
__device__ uint2  g_kaf[(NMAX / 16) * 8 * 4 * 32];  // ka: [rb][chk][nt][lane]
__device__ uint2  g_vsf[(NMAX / 16) * 8 * 32];      // vs=x@Wv: [rb][nt2][lane]
// fp16 B-fragment weight images: uint2 = {half2(k0,k0+1), half2(k0+8,k0+9)} at col n0
__device__ uint2  g_W1f [4096];           // W12 : K=64 [kk=4][ntg=32][lane=32]
__device__ uint2  g_aW2f[4096];           // aW2 : K=256 [kk=16][nt=8][lane=32]
__device__ uint2  g_pW2f[1024];           // pW2 : K=64 [kk=4][nt=8][lane=32]

__device__ __forceinline__ unsigned fp2h2(float a, float b) {
    __half2 h = __floats2half2_rn(a, b);
    return *reinterpret_cast<unsigned*>(&h);
}
__device__ __forceinline__ void mma16(float* c, const unsigned* a, uint2 b) {
    asm volatile("mma.sync.aligned.m16n8k16.row.col.f32.f16.f16.f32 "
                 "{%0,%1,%2,%3}, {%4,%5,%6,%7}, {%8,%9}, {%0,%1,%2,%3};"
                 : "+f"(c[0]), "+f"(c[1]), "+f"(c[2]), "+f"(c[3])
                 : "r"(a[0]), "r"(a[1]), "r"(a[2]), "r"(a[3]), "r"(b.x), "r"(b.y));
}
__device__ __forceinline__ void mma16h(unsigned* d, const unsigned* a, uint2 b) {
    asm volatile("mma.sync.aligned.m16n8k16.row.col.f16.f16.f16.f16 "
                 "{%0,%1}, {%2,%3,%4,%5}, {%6,%7}, {%0,%1};"
                 : "+r"(d[0]), "+r"(d[1])
                 : "r"(a[0]), "r"(a[1]), "r"(a[2]), "r"(a[3]), "r"(b.x), "r"(b.y));
}

// ---------------------------------------------------------------------------
// prep1: weight folds W12 = pW2@aW1, Wqa = Wq@aW1, Wka = Wk@aW1, bqa.
// ---------------------------------------------------------------------------
__global__ void prep1(const float* __restrict__ Wq, const float* __restrict__ Wk,
                      const float* __restrict__ pW2, const float* __restrict__ aW1,
                      const float* __restrict__ ab1, const float* __restrict__ pb2)
{
    __shared__ float srow[3][DD];
    const int r = blockIdx.x, c = threadIdx.x;
    if (c < 64)       srow[0][c]       = Wq [r * DD + c];
    else if (c < 128) srow[1][c - 64]  = Wk [r * DD + (c - 64)];
    else if (c < 192) srow[2][c - 128] = pW2[r * DD + (c - 128)];
    __syncthreads();
    float wq = 0.f, wk = 0.f, w12 = 0.f;
    #pragma unroll 8
    for (int t = 0; t < DD; ++t) {
        float a = aW1[t * HATTN + c];
        wq  = fmaf(srow[0][t], a, wq);
        wk  = fmaf(srow[1][t], a, wk);
        w12 = fmaf(srow[2][t], a, w12);
    }
    g_Wqa[r * HATTN + c] = wq;
    g_Wka[r * HATTN + c] = wk;
    g_W12[r * HATTN + c] = w12;
    if (r == 0) {
        float b = ab1[c];
        for (int t = 0; t < DD; ++t) b = fmaf(pb2[t], aW1[t * HATTN + c], b);
        g_bqa[c] = b;
    }
}

// ---------------------------------------------------------------------------
// prepF: pack W12 / aW2 / pW2 into fp16 B-fragment images (9216 entries).
// ---------------------------------------------------------------------------
__global__ void prepF(const float* __restrict__ aW2, const float* __restrict__ pW2)
{
    const int e = blockIdx.x * 256 + threadIdx.x;
    const int lane = e & 31, gg = lane >> 2, tg = lane & 3;
    if (e < 4096) {                                      // W12, K=64, N=256
        const int kk = e >> 10, nt = (e >> 5) & 31;
        const int k0 = 16 * kk + 2 * tg, n0 = 8 * nt + gg;
        uint2 v;
        v.x = fp2h2(g_W12[(k0    ) * HATTN + n0], g_W12[(k0 + 1) * HATTN + n0]);
        v.y = fp2h2(g_W12[(k0 + 8) * HATTN + n0], g_W12[(k0 + 9) * HATTN + n0]);
        g_W1f[e] = v;
    } else if (e < 8192) {                               // aW2, K=256, N=64
        const int l = e - 4096;
        const int kk = l >> 8, nt = (l >> 5) & 7;
        const int k0 = 16 * kk + 2 * tg, n0 = 8 * nt + gg;
        uint2 v;
        v.x = fp2h2(aW2[(k0    ) * DD + n0], aW2[(k0 + 1) * DD + n0]);
        v.y = fp2h2(aW2[(k0 + 8) * DD + n0], aW2[(k0 + 9) * DD + n0]);
        g_aW2f[l] = v;
    } else if (e < 9216) {                               // pW2, K=64, N=64
        const int l = e - 8192;
        const int kk = l >> 8, nt = (l >> 5) & 7;
        const int k0 = 16 * kk + 2 * tg, n0 = 8 * nt + gg;
        uint2 v;
        v.x = fp2h2(pW2[(k0    ) * DD + n0], pW2[(k0 + 1) * DD + n0]);
        v.y = fp2h2(pW2[(k0 + 8) * DD + n0], pW2[(k0 + 9) * DD + n0]);
        g_pW2f[l] = v;
    }
}

// ---------------------------------------------------------------------------
// prep2: qa (fp32); ka/vs/d in fragment-ordered fp16 images. grid N x 256.
// ---------------------------------------------------------------------------
__global__ void prep2(const float* __restrict__ x, const float* __restrict__ pos,
                      const float* __restrict__ Wv, const float* __restrict__ pW1,
                      int N)
{
    __shared__ float sx[DD];
    const int n = blockIdx.x, c = threadIdx.x;
    if (c < DD) sx[c] = x[n * DD + c];
    __syncthreads();
    float aq = g_bqa[c], ak = 0.f;
    #pragma unroll 8
    for (int t = 0; t < DD; ++t) {
        float xv = sx[t];
        aq = fmaf(xv, g_Wqa[t * HATTN + c], aq);
        ak = fmaf(xv, g_Wka[t * HATTN + c], ak);
    }
    g_qa[n * HATTN + c] = aq;
    const int rb = n >> 4, rr = n & 15, gg = rr & 7, hi = rr >> 3;
    {   // ka fragment image
        const int chk = c >> 5, nt = (c >> 3) & 3, tg = (c & 7) >> 1, lo = c & 1;
        const int ent = ((rb * 8 + chk) * 4 + nt) * 32 + (gg * 4 + tg);
        reinterpret_cast<__half*>(g_kaf)[ent * 4 + hi * 2 + lo] = __float2half(ak);
    }
    if (c < DD) {
        float av = 0.f;
        for (int t = 0; t < DD; ++t) av = fmaf(sx[t], Wv[t * DD + c], av);
        const int nt2 = c >> 3, tg = (c & 7) >> 1, lo = c & 1;
        const int ent = (rb * 8 + nt2) * 32 + (gg * 4 + tg);
        reinterpret_cast<__half*>(g_vsf)[ent * 4 + hi * 2 + lo] = __float2half(av);
        // d fragment image (uint4 entry = {rlo c0, rhi c0, rlo c8, rhi c8} half2s)
        const float dval = fmaf(pos[2 * n], pW1[c], pos[2 * n + 1] * pW1[DD + c]);
        const int w16 = c & 15, kk = c >> 4, tg2 = (w16 & 7) >> 1, lo2 = c & 1;
        const int comp = ((w16 >= 8) ? 2 : 0) + ((rr >= 8) ? 1 : 0);
        const int ent2 = (rb * 4 + kk) * 32 + (gg * 4 + tg2);
        reinterpret_cast<__half*>(g_dff)[ent2 * 8 + comp * 2 + lo2] = __float2half(dval);
    }
}

// ---------------------------------------------------------------------------
// main: grid = 2N; CTA (i = b>>1) covers half the j-range (4 tiles), writes
// S/A partials. Round-11 core + fp16 U build from d-fragment image + d prefetch.
// ---------------------------------------------------------------------------
#define OFF_W1F  0
#define OFF_AW2F 32768
#define OFF_PW2F 65536
#define OFF_QAH  73728
#define OFF_CIH  74240
#define OFF_REDS 74496
#define OFF_REDA 76544
#define SMEM_SZ  78592

__global__ void __launch_bounds__(256, 2)
pt_main(const float* __restrict__ pos, const float* __restrict__ pW1,
        const float* __restrict__ pb1, int N)
{
    extern __shared__ char smem[];
    uint2*   sW1f  = (uint2*)(smem + OFF_W1F);
    uint2*   sAW2f = (uint2*)(smem + OFF_AW2F);
    uint2*   sPW2f = (uint2*)(smem + OFF_PW2F);
    __half2* sQah  = (__half2*)(smem + OFF_QAH);
    __half2* sCih  = (__half2*)(smem + OFF_CIH);
    float*   sRedS = (float*)(smem + OFF_REDS);
    float*   sRedA = (float*)(smem + OFF_REDA);

    const int tid  = threadIdx.x;
    const int i    = blockIdx.x >> 1;
    const int half = blockIdx.x & 1;
    const int w    = tid >> 5, lane = tid & 31;
    const int g    = lane >> 2, tig = lane & 3;

    {   // stage weight fragment images
        uint4* d1 = (uint4*)sW1f;   const uint4* s1 = (const uint4*)g_W1f;
        uint4* d2 = (uint4*)sAW2f;  const uint4* s2 = (const uint4*)g_aW2f;
        uint4* d3 = (uint4*)sPW2f;  const uint4* s3 = (const uint4*)g_pW2f;
        for (int k = tid; k < 2048; k += 256) { d1[k] = s1[k]; d2[k] = s2[k]; }
        for (int k = tid; k < 512;  k += 256) d3[k] = s3[k];
    }
    if (tid < 128) {
        float2 q = *(const float2*)&g_qa[i * HATTN + 2 * tid];
        sQah[tid] = __floats2half2_rn(q.x, q.y);
    }
    const float posIx = pos[2 * i], posIy = pos[2 * i + 1];
    if (tid < 32) {   // ci (pos-MLP hidden pre-activation for query i), half2 pairs
        const int kk = tid >> 3, r = tid & 7, tg = r & 3, hb = r >> 2;
        const int c0 = 16 * kk + 2 * tg + 8 * hb;
        float f0 = fmaf(posIx, pW1[c0],     fmaf(posIy, pW1[DD + c0],     pb1[c0]));
        float f1 = fmaf(posIx, pW1[c0 + 1], fmaf(posIy, pW1[DD + c0 + 1], pb1[c0 + 1]));
        sCih[kk * 8 + hb * 4 + tg] = __floats2half2_rn(f0, f1);
    }
    sRedS[tid] = 0.f; sRedS[tid + 256] = 0.f;
    sRedA[tid] = 0.f; sRedA[tid + 256] = 0.f;
    __syncthreads();

    const __half2 hzero = __float2half2_rn(0.f);
    const int ntile = N >> 7;
    const int jt0 = half * (ntile >> 1);
    const int jt1 = half ? ntile : (ntile >> 1);

    // d-fragment prefetch for the first tile
    uint4 dnx[4];
    {
        const int rb = jt0 * 8 + w;
        #pragma unroll
        for (int kk = 0; kk < 4; ++kk)
            dnx[kk] = __ldg(&g_dff[(rb * 4 + kk) * 32 + lane]);
    }

    for (int jt = jt0; jt < jt1; ++jt) {
        const int rb = jt * 8 + w;
        const uint2* kaRow = &g_kaf[rb * 8 * 4 * 32];
        const uint2* vsRow = &g_vsf[rb * 8 * 32];

        // ---- A fragments: U = relu(ci - d), pure fp16, from prefetched image ----
        unsigned Af[4][4];
        #pragma unroll
        for (int kk = 0; kk < 4; ++kk) {
            const __half2 cl = sCih[kk * 8 + tig];
            const __half2 ch = sCih[kk * 8 + 4 + tig];
            uint4 dv = dnx[kk];
            __half2 u0 = __hmax2(__hsub2(cl, *reinterpret_cast<__half2*>(&dv.x)), hzero);
            __half2 u1 = __hmax2(__hsub2(cl, *reinterpret_cast<__half2*>(&dv.y)), hzero);
            __half2 u2 = __hmax2(__hsub2(ch, *reinterpret_cast<__half2*>(&dv.z)), hzero);
            __half2 u3 = __hmax2(__hsub2(ch, *reinterpret_cast<__half2*>(&dv.w)), hzero);
            Af[kk][0] = *reinterpret_cast<unsigned*>(&u0);
            Af[kk][1] = *reinterpret_cast<unsigned*>(&u1);
            Af[kk][2] = *reinterpret_cast<unsigned*>(&u2);
            Af[kk][3] = *reinterpret_cast<unsigned*>(&u3);
        }

        float sc[8][4];
        #pragma unroll
        for (int a = 0; a < 8; ++a)
            { sc[a][0]=0.f; sc[a][1]=0.f; sc[a][2]=0.f; sc[a][3]=0.f; }

        // ka double-buffer: chunk 0 preloaded; chunk c+1 issued at top of c
        uint2 kac[4];
        #pragma unroll
        for (int nt = 0; nt < 4; ++nt)
            kac[nt] = __ldg(&kaRow[nt * 32 + lane]);

        #pragma unroll 1
        for (int chk = 0; chk < 8; ++chk) {              // 32 attn channels / chunk
            uint2 kan[4];
            const int cn = (chk + 1) & 7;                // wrap: harmless reload at tail
            #pragma unroll
            for (int nt = 0; nt < 4; ++nt)
                kan[nt] = __ldg(&kaRow[(cn * 4 + nt) * 32 + lane]);

            // GEMM1: P = U @ W12 (K=64), fp16 C
            unsigned pa[4][2];
            #pragma unroll
            for (int a = 0; a < 4; ++a) { pa[a][0] = 0u; pa[a][1] = 0u; }
            #pragma unroll
            for (int kk = 0; kk < 4; ++kk) {
                uint2 b0 = sW1f[((kk * 32) + (chk * 4 + 0)) * 32 + lane];
                uint2 b1 = sW1f[((kk * 32) + (chk * 4 + 1)) * 32 + lane];
                uint2 b2 = sW1f[((kk * 32) + (chk * 4 + 2)) * 32 + lane];
                uint2 b3 = sW1f[((kk * 32) + (chk * 4 + 3)) * 32 + lane];
                mma16h(pa[0], Af[kk], b0);
                mma16h(pa[1], Af[kk], b1);
                mma16h(pa[2], Af[kk], b2);
                mma16h(pa[3], Af[kk], b3);
            }
            // epilogue: v = relu(pa + qa - ka); fp16 D layout == GEMM2 A layout
            unsigned a2[2][4];
            #pragma unroll
            for (int nt = 0; nt < 4; ++nt) {
                const __half2 qa2 = sQah[chk * 16 + nt * 4 + tig];
                __half2 qk0 = __hsub2(qa2, *reinterpret_cast<__half2*>(&kac[nt].x));
                __half2 qk1 = __hsub2(qa2, *reinterpret_cast<__half2*>(&kac[nt].y));
                __half2 r0  = __hmax2(__hadd2(*reinterpret_cast<__half2*>(&pa[nt][0]), qk0), hzero);
                __half2 r1  = __hmax2(__hadd2(*reinterpret_cast<__half2*>(&pa[nt][1]), qk1), hzero);
                const int kk2 = nt >> 1, sl = (nt & 1) << 1;
                a2[kk2][sl]     = *reinterpret_cast<unsigned*>(&r0);
                a2[kk2][sl + 1] = *reinterpret_cast<unsigned*>(&r1);
            }
            // GEMM2 partial: sim += P' @ aW2 (K=32 this chunk), fp32 C
            #pragma unroll
            for (int kk2 = 0; kk2 < 2; ++kk2)
                #pragma unroll
                for (int nt2 = 0; nt2 < 8; ++nt2) {
                    uint2 b = sAW2f[(((chk * 2 + kk2) * 8) + nt2) * 32 + lane];
                    mma16(sc[nt2], a2[kk2], b);
                }
            #pragma unroll
            for (int nt = 0; nt < 4; ++nt) kac[nt] = kan[nt];
        }

        // prefetch d fragments for next tile (pa/a2 dead here -> regs free)
        {
            const int jn  = (jt + 1 < jt1) ? jt + 1 : jt0;
            const int rbn = jn * 8 + w;
            #pragma unroll
            for (int kk = 0; kk < 4; ++kk)
                dnx[kk] = __ldg(&g_dff[(rbn * 4 + kk) * 32 + lane]);
        }

        // vs fragments (coalesced LDG.64; overlap GEMM3)
        uint2 vsfr[8];
        #pragma unroll
        for (int nt2 = 0; nt2 < 8; ++nt2)
            vsfr[nt2] = __ldg(&vsRow[nt2 * 32 + lane]);

        // GEMM3: rpe = U @ pW2 (K=64), fp16 C
        unsigned ra[8][2];
        #pragma unroll
        for (int a = 0; a < 8; ++a) { ra[a][0] = 0u; ra[a][1] = 0u; }
        #pragma unroll
        for (int kk = 0; kk < 4; ++kk)
            #pragma unroll
            for (int nt = 0; nt < 8; ++nt) {
                uint2 b = sPW2f[(kk * 8 + nt) * 32 + lane];
                mma16h(ra[nt], Af[kk], b);
            }

        // exp + weighted accumulation, then per-tile reduce over rows
        float Sr[16], Ar[16];
        #pragma unroll
        for (int nt2 = 0; nt2 < 8; ++nt2) {
            __half2 vv0 = __hadd2(*reinterpret_cast<__half2*>(&vsfr[nt2].x),
                                  *reinterpret_cast<__half2*>(&ra[nt2][0]));
            __half2 vv1 = __hadd2(*reinterpret_cast<__half2*>(&vsfr[nt2].y),
                                  *reinterpret_cast<__half2*>(&ra[nt2][1]));
            float2 vl = __half22float2(vv0);
            float2 vh = __half22float2(vv1);
            float e0 = __expf(sc[nt2][0]);
            float e1 = __expf(sc[nt2][1]);
            float e2 = __expf(sc[nt2][2]);
            float e3 = __expf(sc[nt2][3]);
            Sr[nt2 * 2 + 0] = e0 + e2;
            Sr[nt2 * 2 + 1] = e1 + e3;
            Ar[nt2 * 2 + 0] = e0 * vl.x + e2 * vh.x;
            Ar[nt2 * 2 + 1] = e1 * vl.y + e3 * vh.y;
        }
        #pragma unroll
        for (int q = 0; q < 16; ++q) {
            float s = Sr[q], a = Ar[q];
            s += __shfl_xor_sync(0xffffffffu, s, 4);
            a += __shfl_xor_sync(0xffffffffu, a, 4);
            s += __shfl_xor_sync(0xffffffffu, s, 8);
            a += __shfl_xor_sync(0xffffffffu, a, 8);
            s += __shfl_xor_sync(0xffffffffu, s, 16);
            a += __shfl_xor_sync(0xffffffffu, a, 16);
            Sr[q] = s; Ar[q] = a;
        }
        if (lane < 4) {
            #pragma unroll
            for (int nt2 = 0; nt2 < 8; ++nt2) {
                const int d0 = w * DD + nt2 * 8 + 2 * lane;
                sRedS[d0]     += Sr[nt2 * 2 + 0];
                sRedS[d0 + 1] += Sr[nt2 * 2 + 1];
                sRedA[d0]     += Ar[nt2 * 2 + 0];
                sRedA[d0 + 1] += Ar[nt2 * 2 + 1];
            }
        }
    }

    __syncthreads();
    if (tid < DD) {
        float s = 0.f, a = 0.f;
        #pragma unroll
        for (int q = 0; q < 8; ++q) { s += sRedS[q * DD + tid]; a += sRedA[q * DD + tid]; }
        g_part[blockIdx.x * 128 + tid]      = s;
        g_part[blockIdx.x * 128 + 64 + tid] = a;
    }
}

// ---------------------------------------------------------------------------
// combine: out[i][d] = (A0+A1)/(S0+S1) + pb2[d]  (fixed order -> deterministic)
// ---------------------------------------------------------------------------
__global__ void combine(const float* __restrict__ pb2, float* __restrict__ out, int N)
{
    const int i = blockIdx.x, t = threadIdx.x;
    float s = g_part[(2 * i) * 128 + t]      + g_part[(2 * i + 1) * 128 + t];
    float a = g_part[(2 * i) * 128 + 64 + t] + g_part[(2 * i + 1) * 128 + 64 + t];
    out[i * DD + t] = a / s + pb2[t];
}

// ---------------------------------------------------------------------------
extern "C" void kernel_launch(void* const* d_in, const int* in_sizes, int n_in,
                              void* d_out, int out_size)
{
    const float* x   = (const float*)d_in[0];
    const float* pos = (const float*)d_in[1];
    const float* Wq  = (const float*)d_in[2];
    const float* Wk  = (const float*)d_in[3];
    const float* Wv  = (const float*)d_in[4];
    const float* pW1 = (const float*)d_in[5];
    const float* pb1 = (const float*)d_in[6];
    const float* pW2 = (const float*)d_in[7];
    const float* pb2 = (const float*)d_in[8];
    const float* aW1 = (const float*)d_in[9];
    const float* ab1 = (const float*)d_in[10];
    const float* aW2 = (const float*)d_in[11];
    // d_in[12] = ab2: constant over j -> softmax-invariant -> unused.

    const int N = in_sizes[0] / DD;   // B = 1
    float* out  = (float*)d_out;

    prep1<<<DD, 256>>>(Wq, Wk, pW2, aW1, ab1, pb2);
    prepF<<<36, 256>>>(aW2, pW2);
    prep2<<<N, 256>>>(x, pos, Wv, pW1, N);

    cudaFuncSetAttribute((const void*)pt_main,
                         cudaFuncAttributeMaxDynamicSharedMemorySize, SMEM_SZ);
    pt_main<<<2 * N, 256, SMEM_SZ>>>(pos, pW1, pb1, N);
    combine<<<N, DD>>>(pb2, out, N);
}